// round 8
// baseline (speedup 1.0000x reference)
#include <cuda_runtime.h>

#define THREADS 64

// ---------- packed f32x2 helpers ----------
__device__ __forceinline__ unsigned long long pk2(float lo, float hi) {
    unsigned long long r;
    asm("mov.b64 %0, {%1, %2};" : "=l"(r) : "f"(lo), "f"(hi));
    return r;
}
__device__ __forceinline__ void upk2(unsigned long long v, float& lo, float& hi) {
    asm("mov.b64 {%0, %1}, %2;" : "=f"(lo), "=f"(hi) : "l"(v));
}
__device__ __forceinline__ void ffma2(unsigned long long& acc, unsigned long long a, unsigned long long b) {
    asm("fma.rn.f32x2 %0, %1, %2, %0;" : "+l"(acc) : "l"(a), "l"(b));
}
__device__ __forceinline__ unsigned long long mul2(unsigned long long a, unsigned long long b) {
    unsigned long long r; asm("mul.rn.f32x2 %0, %1, %2;" : "=l"(r) : "l"(a), "l"(b)); return r;
}
__device__ __forceinline__ unsigned long long add2(unsigned long long a, unsigned long long b) {
    unsigned long long r; asm("add.rn.f32x2 %0, %1, %2;" : "=l"(r) : "l"(a), "l"(b)); return r;
}
__device__ __forceinline__ float sqrt_ap(float x){ float r; asm("sqrt.approx.f32 %0, %1;" : "=f"(r) : "f"(x)); return r; }
__device__ __forceinline__ float rcp_ap (float x){ float r; asm("rcp.approx.f32 %0, %1;"  : "=f"(r) : "f"(x)); return r; }

// smem float offsets:
//  W  [256][16]                    4096
//  S  [8][8][12]                   768
//  EI [8][16]                      128
//  B  [16]                         16
//  X  union{ 2 x [8k][260 rows],   (GEMM staging, double buffer 2*2080)
//            M [16][16*17] }       4352
#define SM_W  0
#define SM_S  4096
#define SM_EI 4864
#define SM_B  4992
#define SM_X  5008
#define SMEM_FLOATS (5008 + 4352)

__global__ __launch_bounds__(THREADS, 6)
void ocae6(const float* __restrict__ eq,  const float* __restrict__ rei,
           const float* __restrict__ Wg,  const float* __restrict__ bias,
           const float* __restrict__ envdim, const float* __restrict__ envion,
           float* __restrict__ out)
{
    __shared__ float sm[SMEM_FLOATS];
    const int tid = threadIdx.x;
    const int s   = blockIdx.x & 1;
    const int b0  = (blockIdx.x >> 1) * 16;   // 16 batches (256 rows) per block

    // ---------------- stage W, S, EI, B ----------------
    {
        const float4* Wsrc = (const float4*)(Wg + (size_t)s * 4096);
        #pragma unroll
        for (int i = 0; i < 16; i++)
            *(float4*)(sm + SM_W + (tid + 64*i)*4) = __ldg(Wsrc + tid + 64*i);

        #pragma unroll
        for (int u = 0; u < 2; u++) {
            int idx = tid + 64*u;
            sm[SM_EI + idx] = envion[s*128 + idx];
            int ii = idx >> 4, oo = idx & 15;
            const float* A = envdim + s*1152 + ii*144 + oo*9;
            float a00=A[0],a01=A[1],a02=A[2], a10=A[3],a11=A[4],a12=A[5], a20=A[6],a21=A[7],a22=A[8];
            float s00 = a00*a00 + a10*a10 + a20*a20;
            float s11 = a01*a01 + a11*a11 + a21*a21;
            float s22 = a02*a02 + a12*a12 + a22*a22;
            float s01 = 2.f*(a00*a01 + a10*a11 + a20*a21);
            float s02 = 2.f*(a00*a02 + a10*a12 + a20*a22);
            float s12 = 2.f*(a01*a02 + a11*a12 + a21*a22);
            float* dst = sm + SM_S + (ii*8 + (oo>>1))*12 + (oo&1);
            dst[0]=s00; dst[2]=s11; dst[4]=s22; dst[6]=s01; dst[8]=s02; dst[10]=s12;
        }
        if (tid < 16) sm[SM_B + tid] = bias[s*16 + tid];
    }

    const int rg = tid >> 1;     // row group 0..31 -> rows rg*8 .. rg*8+7
    const int oh = tid & 1;      // orbital half: orbs [8*oh, 8*oh+8)

    // this thread's 8 rows live in ONE matrix: m = rg>>1, n = (rg&1)*8 + j
    const size_t growR = ((size_t)(b0 + (rg>>1)))*32 + s*16 + (size_t)((rg&1)*8);

    // staging map: thread owns float4 f = tid + 64*j of each 8-k chunk
    const float4* gp[8];
    int so[8];
    #pragma unroll
    for (int j = 0; j < 8; j++) {
        int f  = tid + 64*j;        // 0..511
        int kq = f & 1;             // which float4 (k quad) within chunk
        int rw = f >> 1;            // block row 0..255
        size_t gr = ((size_t)(b0 + (rw>>4)))*32 + s*16 + (rw&15);
        gp[j] = (const float4*)eq + gr*64 + kq;
        so[j] = kq*1040 + rw;       // + e*260 per k within quad
    }

    float4 pre[8];
    #pragma unroll
    for (int j = 0; j < 8; j++) pre[j] = __ldg(gp[j]);          // chunk 0
    __syncthreads();   // constants staged (W needed by compute; X clean)

    #pragma unroll
    for (int j = 0; j < 8; j++) {                               // store chunk 0 -> buf0
        float v[4]; *(float4*)v = pre[j];
        float* base = sm + SM_X + so[j];
        base[0] = v[0]; base[260] = v[1]; base[520] = v[2]; base[780] = v[3];
    }
    #pragma unroll
    for (int j = 0; j < 8; j++) pre[j] = __ldg(gp[j] + 2);      // chunk 1
    __syncthreads();   // buf0 ready

    unsigned long long acc[32];
    #pragma unroll
    for (int i = 0; i < 32; i++) acc[i] = 0ull;

    // ---------------- GEMM: 32 chunks of 8 k, double-buffered ----------------
    #pragma unroll 1
    for (int c = 0; c < 32; c++) {
        const float* xb = sm + SM_X + (c & 1)*2080;
        #pragma unroll
        for (int k = 0; k < 8; k++) {
            float xr[8];
            *(float4*)(xr)     = *(const float4*)(xb + k*260 + rg*8);
            *(float4*)(xr + 4) = *(const float4*)(xb + k*260 + rg*8 + 4);
            const ulonglong2* wp = (const ulonglong2*)(sm + SM_W + (c*8 + k)*16 + oh*8);
            ulonglong2 wA = wp[0], wB = wp[1];
            #pragma unroll
            for (int j = 0; j < 8; j++) {
                unsigned long long xx = pk2(xr[j], xr[j]);
                ffma2(acc[j*4+0], xx, wA.x);
                ffma2(acc[j*4+1], xx, wA.y);
                ffma2(acc[j*4+2], xx, wB.x);
                ffma2(acc[j*4+3], xx, wB.y);
            }
        }
        if (c < 31) {
            // store chunk c+1 into the buffer freed at the previous barrier
            float* bb = sm + SM_X + ((c+1) & 1)*2080;
            #pragma unroll
            for (int j = 0; j < 8; j++) {
                float v[4]; *(float4*)v = pre[j];
                float* base = bb + so[j];
                base[0] = v[0]; base[260] = v[1]; base[520] = v[2]; base[780] = v[3];
            }
            if (c < 30) {
                #pragma unroll
                for (int j = 0; j < 8; j++) pre[j] = __ldg(gp[j] + (c+2)*2);
            }
        }
        __syncthreads();
    }
    // last barrier also protects M-over-X reuse below

    // ---------------- env + M (8 rows, own accumulators) ----------------
    {
        const float4* rbase = (const float4*)rei + growR*6;
        float4 rv4[6];
        #pragma unroll
        for (int q = 0; q < 6; q++) rv4[q] = __ldg(rbase + q);

        const int m = rg >> 1;
        float* Mrow = sm + SM_X + m*272 + (rg&1)*8;    // + j for column n

        #pragma unroll 1
        for (int j = 0; j < 8; j++) {
            float rv[24];
            #pragma unroll
            for (int q = 0; q < 6; q++) *(float4*)(rv + q*4) = rv4[q];
            if (j < 7) {
                #pragma unroll
                for (int q = 0; q < 6; q++) rv4[q] = __ldg(rbase + (j+1)*6 + q);
            }
            unsigned long long ev[4] = {0,0,0,0};
            #pragma unroll
            for (int i = 0; i < 8; i++) {
                float r0 = rv[i*3], r1 = rv[i*3+1], r2 = rv[i*3+2];
                unsigned long long p00 = pk2(r0*r0, r0*r0);
                unsigned long long p11 = pk2(r1*r1, r1*r1);
                unsigned long long p22 = pk2(r2*r2, r2*r2);
                unsigned long long p01 = pk2(r0*r1, r0*r1);
                unsigned long long p02 = pk2(r0*r2, r0*r2);
                unsigned long long p12 = pk2(r1*r2, r1*r2);
                const float* Sb = sm + SM_S + i*96 + oh*48;
                const unsigned long long* Eb = (const unsigned long long*)(sm + SM_EI) + i*8 + oh*4;
                #pragma unroll
                for (int op = 0; op < 4; op++) {
                    const ulonglong2* Sp = (const ulonglong2*)(Sb + op*12);
                    ulonglong2 sA = Sp[0], sB = Sp[1], sC = Sp[2];
                    unsigned long long q = 0ull;
                    ffma2(q, sA.x, p00); ffma2(q, sA.y, p11); ffma2(q, sB.x, p22);
                    ffma2(q, sB.y, p01); ffma2(q, sC.x, p02); ffma2(q, sC.y, p12);
                    float q0, q1; upk2(q, q0, q1);
                    float e0 = __expf(-sqrt_ap(fmaxf(q0, 0.f)));
                    float e1 = __expf(-sqrt_ap(fmaxf(q1, 0.f)));
                    ffma2(ev[op], pk2(e0, e1), Eb[op]);
                }
            }
            #pragma unroll
            for (int op = 0; op < 4; op++) {
                unsigned long long bb2 = *(const unsigned long long*)(sm + SM_B + (oh*4+op)*2);
                unsigned long long mm = mul2(add2(acc[j*4+op], bb2), ev[op]);
                float m0, m1; upk2(mm, m0, m1);
                Mrow[(oh*8 + 2*op)*17 + j]     = m0;
                Mrow[(oh*8 + 2*op + 1)*17 + j] = m1;
            }
        }
    }
    __syncthreads();

    // ---------------- cofactors: register LU, 4 passes x 2 segments per warp ----------------
    const unsigned FULL = 0xffffffffu;
    const int lane = tid & 31;
    const int w    = tid >> 5;
    const int seg  = lane >> 4;
    const int o    = lane & 15;

    #pragma unroll 1
    for (int ip = 0; ip < 4; ip++) {
        const int m = ip*4 + w*2 + seg;
        float a[17];
        {
            const float* Ma = sm + SM_X + m*272 + o*17;
            #pragma unroll
            for (int j = 0; j < 16; j++) a[j] = Ma[j];
            a[16] = (o == 0) ? 1.f : 0.f;    // rhs e0
        }
        float det = 1.f;

        #pragma unroll
        for (int k = 0; k < 16; k++) {
            float v = (o >= k) ? fabsf(a[k]) : -1.f;
            int   p = o;
            #pragma unroll
            for (int off = 8; off; off >>= 1) {
                float ov = __shfl_xor_sync(FULL, v, off, 16);
                int   oq = __shfl_xor_sync(FULL, p, off, 16);
                if (ov > v || (ov == v && oq < p)) { v = ov; p = oq; }
            }
            float pvk = __shfl_sync(FULL, a[k], p, 16);
            float kvk = __shfl_sync(FULL, a[k], k, 16);
            if (o == k) a[k] = pvk; else if (o == p) a[k] = kvk;
            det = (p != k) ? -det : det;
            det *= pvk;
            float mlt = (o > k) ? a[k] * rcp_ap(pvk) : 0.f;
            #pragma unroll
            for (int j = k + 1; j < 17; j++) {
                float pv = __shfl_sync(FULL, a[j], p, 16);
                float kv = __shfl_sync(FULL, a[j], k, 16);
                if (o == k) a[j] = pv; else if (o == p) a[j] = kv;
                a[j] -= mlt * pv;
            }
        }

        // back-substitution: U z = rhs
        float z = 0.f, rhs = a[16];
        #pragma unroll
        for (int k = 15; k >= 0; k--) {
            float num = __shfl_sync(FULL, rhs,  k, 16);
            float den = __shfl_sync(FULL, a[k], k, 16);
            float xk = num * rcp_ap(den);
            if (o == k) z = xk;
            rhs -= a[k] * xk;
        }

        float c0 = sm[SM_X + m*272 + o];   // M[o][0]
        out[((size_t)(b0 + m)*2 + s)*16 + o] = c0 * det * z;
    }
}

extern "C" void kernel_launch(void* const* d_in, const int* in_sizes, int n_in,
                              void* d_out, int out_size)
{
    const float* eq  = (const float*)d_in[0];
    const float* rei = (const float*)d_in[1];
    const float* W   = (const float*)d_in[2];
    const float* b   = (const float*)d_in[3];
    const float* ed  = (const float*)d_in[4];
    const float* ei  = (const float*)d_in[5];
    float* out = (float*)d_out;

    int B = in_sizes[0] / (32 * 256);        // 4096
    dim3 grid((B / 16) * 2);                 // 16 batches x 1 spin per block
    ocae6<<<grid, THREADS>>>(eq, rei, W, b, ed, ei, out);
}

// round 9
// speedup vs baseline: 1.6153x; 1.6153x over previous
#include <cuda_runtime.h>

#define THREADS 128

// ---------- packed f32x2 helpers ----------
__device__ __forceinline__ unsigned long long pk2(float lo, float hi) {
    unsigned long long r;
    asm("mov.b64 %0, {%1, %2};" : "=l"(r) : "f"(lo), "f"(hi));
    return r;
}
__device__ __forceinline__ void upk2(unsigned long long v, float& lo, float& hi) {
    asm("mov.b64 {%0, %1}, %2;" : "=f"(lo), "=f"(hi) : "l"(v));
}
__device__ __forceinline__ void ffma2(unsigned long long& acc, unsigned long long a, unsigned long long b) {
    asm("fma.rn.f32x2 %0, %1, %2, %0;" : "+l"(acc) : "l"(a), "l"(b));
}
__device__ __forceinline__ unsigned long long mul2(unsigned long long a, unsigned long long b) {
    unsigned long long r; asm("mul.rn.f32x2 %0, %1, %2;" : "=l"(r) : "l"(a), "l"(b)); return r;
}
__device__ __forceinline__ unsigned long long add2(unsigned long long a, unsigned long long b) {
    unsigned long long r; asm("add.rn.f32x2 %0, %1, %2;" : "=l"(r) : "l"(a), "l"(b)); return r;
}
__device__ __forceinline__ float sqrt_ap(float x){ float r; asm("sqrt.approx.f32 %0, %1;" : "=f"(r) : "f"(x)); return r; }
__device__ __forceinline__ float rcp_ap (float x){ float r; asm("rcp.approx.f32 %0, %1;"  : "=f"(r) : "f"(x)); return r; }

// smem float offsets:
//  W  [256][16]                     4096
//  S  [8][8][12]                    768
//  EI [8][16]                       128
//  B  [16]                          16
//  X  2 x [256 rows][12]            6144  (8k chunk staging, stride 12, double buffer)
//     (M [16][16*17]=4352 overlays X after GEMM)
#define SM_W  0
#define SM_S  4096
#define SM_EI 4864
#define SM_B  4992
#define SM_X  5008
#define SMEM_FLOATS (5008 + 6144)

__global__ __launch_bounds__(THREADS, 4)
void ocae7(const float* __restrict__ eq,  const float* __restrict__ rei,
           const float* __restrict__ Wg,  const float* __restrict__ bias,
           const float* __restrict__ envdim, const float* __restrict__ envion,
           float* __restrict__ out)
{
    __shared__ __align__(16) float sm[SMEM_FLOATS];
    const int tid = threadIdx.x;
    const int s   = blockIdx.x & 1;
    const int b0  = (blockIdx.x >> 1) * 16;   // 16 batch-spins (256 rows) per block

    // ---------------- stage W, S, EI, B ----------------
    {
        const float4* Wsrc = (const float4*)(Wg + (size_t)s * 4096);
        #pragma unroll
        for (int i = 0; i < 8; i++)
            *(float4*)(sm + SM_W + (tid + 128*i)*4) = __ldg(Wsrc + tid + 128*i);

        if (tid < 128) {
            sm[SM_EI + tid] = envion[s*128 + tid];
            int ii = tid >> 4, oo = tid & 15;
            const float* A = envdim + s*1152 + ii*144 + oo*9;
            float a00=A[0],a01=A[1],a02=A[2], a10=A[3],a11=A[4],a12=A[5], a20=A[6],a21=A[7],a22=A[8];
            float s00 = a00*a00 + a10*a10 + a20*a20;
            float s11 = a01*a01 + a11*a11 + a21*a21;
            float s22 = a02*a02 + a12*a12 + a22*a22;
            float s01 = 2.f*(a00*a01 + a10*a11 + a20*a21);
            float s02 = 2.f*(a00*a02 + a10*a12 + a20*a22);
            float s12 = 2.f*(a01*a02 + a11*a12 + a21*a22);
            float* dst = sm + SM_S + (ii*8 + (oo>>1))*12 + (oo&1);
            dst[0]=s00; dst[2]=s11; dst[4]=s22; dst[6]=s01; dst[8]=s02; dst[10]=s12;
        }
        if (tid < 16) sm[SM_B + tid] = bias[s*16 + tid];
    }

    const int rg = tid >> 1;     // row group 0..63
    const int oh = tid & 1;      // orbital half: orbs [8*oh, 8*oh+8)
    // thread's 4 rows: r_j = rg + 64*j

    // staging map: thread owns float4 f = tid + 128*u of each 8-k chunk (512 f4 total)
    const float4* gp[4];
    int so[4];
    #pragma unroll
    for (int u = 0; u < 4; u++) {
        int f  = tid + 128*u;       // 0..511
        int kq = f & 1;             // k-quad within chunk
        int rw = f >> 1;            // block row 0..255
        size_t gr = ((size_t)(b0 + (rw>>4)))*32 + s*16 + (rw&15);
        gp[u] = (const float4*)eq + gr*64 + kq;
        so[u] = SM_X + rw*12 + kq*4;
    }

    float4 pre[4];
    #pragma unroll
    for (int u = 0; u < 4; u++) pre[u] = __ldg(gp[u]);          // chunk 0
    __syncthreads();                                            // constants staged

    #pragma unroll
    for (int u = 0; u < 4; u++) *(float4*)(sm + so[u]) = pre[u];  // chunk 0 -> buf0
    #pragma unroll
    for (int u = 0; u < 4; u++) pre[u] = __ldg(gp[u] + 2);      // chunk 1
    __syncthreads();                                            // buf0 ready

    unsigned long long acc[16];
    #pragma unroll
    for (int i = 0; i < 16; i++) acc[i] = 0ull;

    // ---------------- GEMM: 32 chunks of 8 k, double-buffered, 1 barrier/chunk ----------------
    #pragma unroll 1
    for (int c = 0; c < 32; c++) {
        if (c < 31) {
            float* bb = sm + ((c+1) & 1)*3072;   // buffer freed by the previous barrier
            #pragma unroll
            for (int u = 0; u < 4; u++) *(float4*)(bb + so[u]) = pre[u];
            if (c < 30) {
                #pragma unroll
                for (int u = 0; u < 4; u++) pre[u] = __ldg(gp[u] + (c+2)*2);
            }
        }
        const float* xb = sm + SM_X + (c & 1)*3072;
        #pragma unroll
        for (int kq = 0; kq < 2; kq++) {
            float xv[4][4];
            #pragma unroll
            for (int j = 0; j < 4; j++)
                *(float4*)xv[j] = *(const float4*)(xb + (rg + 64*j)*12 + kq*4);
            #pragma unroll
            for (int e = 0; e < 4; e++) {
                const ulonglong2* wp = (const ulonglong2*)(sm + SM_W + (c*8 + kq*4 + e)*16 + oh*8);
                ulonglong2 wA = wp[0], wB = wp[1];
                #pragma unroll
                for (int j = 0; j < 4; j++) {
                    unsigned long long xx = pk2(xv[j][e], xv[j][e]);
                    ffma2(acc[j*4+0], xx, wA.x);
                    ffma2(acc[j*4+1], xx, wA.y);
                    ffma2(acc[j*4+2], xx, wB.x);
                    ffma2(acc[j*4+3], xx, wB.y);
                }
            }
        }
        __syncthreads();
    }
    // after final barrier all warps are done with X -> M may overlay it

    // ---------------- env + M (4 rows, own accumulators) ----------------
    #pragma unroll 1
    for (int j = 0; j < 4; j++) {
        const int r = rg + 64*j;
        const size_t grow = ((size_t)(b0 + (r>>4)))*32 + s*16 + (r&15);
        float rv[24];
        {
            const float4* rp = (const float4*)rei + grow*6;
            #pragma unroll
            for (int q = 0; q < 6; q++) *(float4*)(rv + q*4) = __ldg(rp + q);
        }
        unsigned long long ev[4] = {0,0,0,0};
        #pragma unroll
        for (int i = 0; i < 8; i++) {
            float r0 = rv[i*3], r1 = rv[i*3+1], r2 = rv[i*3+2];
            unsigned long long p00 = pk2(r0*r0, r0*r0);
            unsigned long long p11 = pk2(r1*r1, r1*r1);
            unsigned long long p22 = pk2(r2*r2, r2*r2);
            unsigned long long p01 = pk2(r0*r1, r0*r1);
            unsigned long long p02 = pk2(r0*r2, r0*r2);
            unsigned long long p12 = pk2(r1*r2, r1*r2);
            const float* Sb = sm + SM_S + i*96 + oh*48;
            const unsigned long long* Eb = (const unsigned long long*)(sm + SM_EI) + i*8 + oh*4;
            #pragma unroll
            for (int op = 0; op < 4; op++) {
                const ulonglong2* Sp = (const ulonglong2*)(Sb + op*12);
                ulonglong2 sA = Sp[0], sB = Sp[1], sC = Sp[2];
                unsigned long long q = 0ull;
                ffma2(q, sA.x, p00); ffma2(q, sA.y, p11); ffma2(q, sB.x, p22);
                ffma2(q, sB.y, p01); ffma2(q, sC.x, p02); ffma2(q, sC.y, p12);
                float q0, q1; upk2(q, q0, q1);
                float e0 = __expf(-sqrt_ap(fmaxf(q0, 0.f)));
                float e1 = __expf(-sqrt_ap(fmaxf(q1, 0.f)));
                ffma2(ev[op], pk2(e0, e1), Eb[op]);
            }
        }
        const int m = r >> 4, n = r & 15;
        float* Mb = sm + SM_X + m*272 + n;     // M overlays X
        #pragma unroll
        for (int op = 0; op < 4; op++) {
            unsigned long long bb2 = *(const unsigned long long*)(sm + SM_B + (oh*4+op)*2);
            unsigned long long mm = mul2(add2(acc[j*4+op], bb2), ev[op]);
            float m0, m1; upk2(mm, m0, m1);
            Mb[(oh*8 + 2*op)*17]     = m0;     // (M^T)[o][n]
            Mb[(oh*8 + 2*op + 1)*17] = m1;
        }
    }
    __syncthreads();

    // ---------------- cofactors: register LU, 2 passes x 2 segments per warp ----------------
    const unsigned FULL = 0xffffffffu;
    const int lane = tid & 31;
    const int w    = tid >> 5;
    const int seg  = lane >> 4;
    const int o    = lane & 15;

    #pragma unroll 1
    for (int ip = 0; ip < 2; ip++) {
        const int m = ip*8 + w*2 + seg;
        float a[17];
        {
            const float* Ma = sm + SM_X + m*272 + o*17;
            #pragma unroll
            for (int j = 0; j < 16; j++) a[j] = Ma[j];
            a[16] = (o == 0) ? 1.f : 0.f;    // rhs e0
        }
        float det = 1.f;

        #pragma unroll
        for (int k = 0; k < 16; k++) {
            float v = (o >= k) ? fabsf(a[k]) : -1.f;
            int   p = o;
            #pragma unroll
            for (int off = 8; off; off >>= 1) {
                float ov = __shfl_xor_sync(FULL, v, off, 16);
                int   oq = __shfl_xor_sync(FULL, p, off, 16);
                if (ov > v || (ov == v && oq < p)) { v = ov; p = oq; }
            }
            float pvk = __shfl_sync(FULL, a[k], p, 16);
            float kvk = __shfl_sync(FULL, a[k], k, 16);
            if (o == k) a[k] = pvk; else if (o == p) a[k] = kvk;
            det = (p != k) ? -det : det;
            det *= pvk;
            float mlt = (o > k) ? a[k] * rcp_ap(pvk) : 0.f;
            #pragma unroll
            for (int j = k + 1; j < 17; j++) {
                float pv = __shfl_sync(FULL, a[j], p, 16);
                float kv = __shfl_sync(FULL, a[j], k, 16);
                if (o == k) a[j] = pv; else if (o == p) a[j] = kv;
                a[j] -= mlt * pv;
            }
        }

        // back-substitution: U z = rhs
        float z = 0.f, rhs = a[16];
        #pragma unroll
        for (int k = 15; k >= 0; k--) {
            float num = __shfl_sync(FULL, rhs,  k, 16);
            float den = __shfl_sync(FULL, a[k], k, 16);
            float xk = num * rcp_ap(den);
            if (o == k) z = xk;
            rhs -= a[k] * xk;
        }

        float c0 = sm[SM_X + m*272 + o];   // M[o][0]
        out[((size_t)(b0 + m)*2 + s)*16 + o] = c0 * det * z;
    }
}

extern "C" void kernel_launch(void* const* d_in, const int* in_sizes, int n_in,
                              void* d_out, int out_size)
{
    const float* eq  = (const float*)d_in[0];
    const float* rei = (const float*)d_in[1];
    const float* W   = (const float*)d_in[2];
    const float* b   = (const float*)d_in[3];
    const float* ed  = (const float*)d_in[4];
    const float* ei  = (const float*)d_in[5];
    float* out = (float*)d_out;

    int B = in_sizes[0] / (32 * 256);        // 4096
    dim3 grid((B / 16) * 2);                 // 16 batch-spins per block
    ocae7<<<grid, THREADS>>>(eq, rei, W, b, ed, ei, out);
}